// round 8
// baseline (speedup 1.0000x reference)
#include <cuda_runtime.h>
#include <cuda_bf16.h>
#include <math.h>
#include <stdint.h>

// Problem constants
#define B_   4
#define U_   8192
#define E_   128
#define GH_  64
#define GW_  64
#define S_   (GH_*GW_)        // 4096
#define NB_  (B_*S_)          // 16384 buckets
#define NOFF (B_*U_)          // 32768 off-grid tokens
#define CAP_ 23               // MAX_PATCH-1 usable slots

// ---------------- scratch (device globals; no cudaMalloc allowed) ----------
__device__ float g_Koff[NOFF*E_];   // 16 MB
__device__ float g_Voff[NOFF*E_];   // 16 MB
__device__ float g_Kon [NB_*E_];    // 8 MB
__device__ float g_Von [NB_*E_];    // 8 MB
__device__ float g_Q   [S_*E_];     // 2 MB (shared across batch)
__device__ int   g_counts[NB_];
__device__ int   g_members[NB_*CAP_];
__device__ float g_Kfake[E_];
__device__ float g_Vfake[E_];
// Pre-split bf16 weights, transposed + k-pair-packed for the mma B fragment:
// g_Wp[w][p][kk*128 + n] = bf16(W[2kk][n]) | bf16(W[2kk+1][n])<<16
// w: 0=Wq 1=Wk 2=Wv 3=Wo ; p: 0=hi 1=lo(residual)
__device__ uint32_t g_Wp[4][2][64*128];

// ---------------- helpers ----------------------------------------------------
__device__ __forceinline__ uint32_t pk2(float x, float y) {
    uint32_t lo = (uint32_t)__bfloat16_as_ushort(__float2bfloat16(x));
    uint32_t hi = (uint32_t)__bfloat16_as_ushort(__float2bfloat16(y));
    return lo | (hi << 16);
}
__device__ __forceinline__ float resid(float x) {
    return x - __bfloat162float(__float2bfloat16(x));
}
__device__ __forceinline__ void mma16816(float* c, const uint32_t* a,
                                         uint32_t b0, uint32_t b1) {
    asm volatile(
        "mma.sync.aligned.m16n8k16.row.col.f32.bf16.bf16.f32 "
        "{%0,%1,%2,%3}, {%4,%5,%6,%7}, {%8,%9}, {%0,%1,%2,%3};"
        : "+f"(c[0]), "+f"(c[1]), "+f"(c[2]), "+f"(c[3])
        : "r"(a[0]), "r"(a[1]), "r"(a[2]), "r"(a[3]), "r"(b0), "r"(b1));
}

#define WROW 136
#define SM_WORDS (2 * 64 * WROW)          // 17408 u32 = 69632 B
#define W_BYTES (SM_WORDS * 4)            // 69632
#define AROW 132
#define A_BYTES (64 * AROW * 4)           // 33792
#define FUSED_SMEM (W_BYTES + A_BYTES + 8 * 24 * 4)

// ---------------- Stage 1 (fused prep): wsplit + bucketize + fake proj ------
__global__ void __launch_bounds__(256) prep_kernel(const float* __restrict__ Wq,
                                                   const float* __restrict__ Wk,
                                                   const float* __restrict__ Wv,
                                                   const float* __restrict__ Wo,
                                                   const float* __restrict__ xoff,
                                                   const float* __restrict__ xon,
                                                   const float* __restrict__ fake) {
    const int blk = blockIdx.x;
    const int tid = threadIdx.x;

    if (blk < 4) {
        // ---- weight split/pack ----
        const float* W = (blk == 0) ? Wq : (blk == 1) ? Wk : (blk == 2) ? Wv : Wo;
        uint32_t* dh = g_Wp[blk][0];
        uint32_t* dl = g_Wp[blk][1];
        for (int idx = tid; idx < 64 * 128; idx += 256) {
            int kk = idx >> 7;
            int n  = idx & 127;
            float w0 = W[(2*kk)   * 128 + n];
            float w1 = W[(2*kk+1) * 128 + n];
            dh[idx] = pk2(w0, w1);
            dl[idx] = pk2(resid(w0), resid(w1));
        }
    } else if (blk < 132) {
        // ---- bucket assignment ----
        int i = (blk - 4) * 256 + tid;
        float ay0 = xon[0];
        float ay1 = xon[2*GW_];
        float ax0 = xon[1];
        float ax1 = xon[3];
        float x0 = xoff[2*i+0];
        float x1 = xoff[2*i+1];
        float r0 = rintf(__fdiv_rn(x0 - ay0, ay1 - ay0));
        float r1 = rintf(__fdiv_rn(x1 - ax0, ax1 - ax0));
        int i0 = (int)fminf(fmaxf(r0, 0.0f), (float)(GH_-1));
        int i1 = (int)fminf(fmaxf(r1, 0.0f), (float)(GW_-1));
        int flat = (i / U_) * S_ + i0 * GW_ + i1;
        int slot = atomicAdd(&g_counts[flat], 1);
        if (slot < CAP_) g_members[flat*CAP_ + slot] = i;
    } else {
        // ---- fake projection: 8 blocks x 8 warps = 64 warps, 4 outputs each
        const int wid  = tid >> 5;
        const int lane = tid & 31;
        const int fw = (blk - 132) * 8 + wid;      // 0..63
        float f0 = fake[lane];
        float f1 = fake[lane + 32];
        float f2 = fake[lane + 64];
        float f3 = fake[lane + 96];
#pragma unroll
        for (int t = 0; t < 4; t++) {
            int o = fw * 4 + t;                    // 0..255
            int col = o & 127;
            const float* W = (o < 128) ? Wk : Wv;
            float s = f0 * W[lane*128 + col]
                    + f1 * W[(lane+32)*128 + col]
                    + f2 * W[(lane+64)*128 + col]
                    + f3 * W[(lane+96)*128 + col];
#pragma unroll
            for (int d = 16; d > 0; d >>= 1)
                s += __shfl_xor_sync(0xffffffffu, s, d);
            if (lane == 0) {
                if (o < 128) g_Kfake[col] = s;
                else         g_Vfake[col] = s;
            }
        }
    }
}

// ---------------- Stage 2: phase-1 bf16-split HMMA GEMM (1 tile / CTA) ------
// D = Ah*Wh + Ah*Wl + Al*Wh, fp32 accum, depth-1 A prefetch over k-chunks.
__global__ void __launch_bounds__(256, 3) gemm_mma(const float* __restrict__ zoff,
                                                   const float* __restrict__ zon,
                                                   const float* __restrict__ lat) {
    extern __shared__ uint32_t sw[];       // [0..8703]=hi, [8704..]=lo
    const int tid = threadIdx.x;
    const int blk = blockIdx.x;

    // ---- job decode (64 rows per CTA) ----
    int wsel;
    const float* A;
    float* C;
    if (blk < 512) {
        wsel = 1; A = zoff + (size_t)blk * 64 * E_;        C = g_Koff + (size_t)blk * 64 * E_;
    } else if (blk < 1024) {
        wsel = 2; A = zoff + (size_t)(blk-512) * 64 * E_;  C = g_Voff + (size_t)(blk-512) * 64 * E_;
    } else if (blk < 1280) {
        wsel = 1; A = zon + (size_t)(blk-1024) * 64 * E_;  C = g_Kon + (size_t)(blk-1024) * 64 * E_;
    } else if (blk < 1536) {
        wsel = 2; A = zon + (size_t)(blk-1280) * 64 * E_;  C = g_Von + (size_t)(blk-1280) * 64 * E_;
    } else {
        wsel = 0; A = lat + (size_t)(blk-1536) * 64 * E_;  C = g_Q + (size_t)(blk-1536) * 64 * E_;
    }

    // ---- load packed W hi/lo into padded smem ----
    {
        const float4* srcH = (const float4*)g_Wp[wsel][0];
        const float4* srcL = (const float4*)g_Wp[wsel][1];
#pragma unroll
        for (int i = tid; i < 2048; i += 256) {
            int row = i >> 5;
            int c4  = i & 31;
            *(float4*)&sw[row*WROW + c4*4]        = srcH[i];
            *(float4*)&sw[8704 + row*WROW + c4*4] = srcL[i];
        }
    }
    __syncthreads();

    // ---- warp tiling: 8 warps = 4 (M) x 2 (N); warp tile 16x64 ----
    const int wid  = tid >> 5;
    const int lane = tid & 31;
    const int m0 = (wid & 3) * 16;
    const int n0 = (wid >> 2) * 64;
    const int g = lane >> 2;             // 0..7
    const int c = lane & 3;              // 0..3

    float acc[8][4];
#pragma unroll
    for (int i = 0; i < 8; i++)
#pragma unroll
        for (int j = 0; j < 4; j++) acc[i][j] = 0.f;

    const float* ar = A + (m0 + g) * E_ + 2*c;
    // prefetch chunk 0
    float2 x0 = *(const float2*)ar;
    float2 x1 = *(const float2*)(ar + 8*E_);
    float2 x2 = *(const float2*)(ar + 8);
    float2 x3 = *(const float2*)(ar + 8*E_ + 8);

#pragma unroll
    for (int kc = 0; kc < 8; kc++) {
        float2 y0, y1, y2, y3;
        if (kc < 7) {                       // depth-1 prefetch of next chunk
            const float* an = ar + (kc+1)*16;
            y0 = *(const float2*)an;
            y1 = *(const float2*)(an + 8*E_);
            y2 = *(const float2*)(an + 8);
            y3 = *(const float2*)(an + 8*E_ + 8);
        }
        uint32_t ah[4], al[4];
        ah[0] = pk2(x0.x, x0.y);  al[0] = pk2(resid(x0.x), resid(x0.y));
        ah[1] = pk2(x1.x, x1.y);  al[1] = pk2(resid(x1.x), resid(x1.y));
        ah[2] = pk2(x2.x, x2.y);  al[2] = pk2(resid(x2.x), resid(x2.y));
        ah[3] = pk2(x3.x, x3.y);  al[3] = pk2(resid(x3.x), resid(x3.y));

        const int brow = kc * 8 + c;
#pragma unroll
        for (int nt = 0; nt < 8; nt++) {
            int col = n0 + nt*8 + g;
            uint32_t bh0 = sw[brow*WROW + col];
            uint32_t bh1 = sw[(brow+4)*WROW + col];
            uint32_t bl0 = sw[8704 + brow*WROW + col];
            uint32_t bl1 = sw[8704 + (brow+4)*WROW + col];
            mma16816(acc[nt], ah, bh0, bh1);
            mma16816(acc[nt], ah, bl0, bl1);
            mma16816(acc[nt], al, bh0, bh1);
        }
        if (kc < 7) { x0 = y0; x1 = y1; x2 = y2; x3 = y3; }
    }

    // ---- epilogue ----
#pragma unroll
    for (int nt = 0; nt < 8; nt++) {
        int colb = n0 + nt*8 + 2*c;
        *(float2*)&C[(m0 + g) * E_ + colb]     = make_float2(acc[nt][0], acc[nt][1]);
        *(float2*)&C[(m0 + g + 8) * E_ + colb] = make_float2(acc[nt][2], acc[nt][3]);
    }
}

// ---------------- Stage 3: fused attention + Wo projection ------------------
// 256 CTAs x 64 buckets. Each warp: online-softmax attention for 8 buckets ->
// smem A tile; then the 8-warp HMMA GEMM consumes A from smem and writes out.
__global__ void __launch_bounds__(256) fused_attn_wo(const int* __restrict__ ign_p,
                                                     float* __restrict__ out) {
    extern __shared__ uint8_t sm[];
    uint32_t* sw  = (uint32_t*)sm;                 // W hi/lo (69632 B)
    float*    As  = (float*)(sm + W_BYTES);        // attention tile 64 x AROW
    int*      mb  = (int*)(sm + W_BYTES + A_BYTES);// members: 8 warps x 24

    const int tid = threadIdx.x;
    const int wid = tid >> 5;
    const int lane = tid & 31;
    const int blk = blockIdx.x;
    const int ign = *ign_p;

    // ---- load packed Wo hi/lo into smem (overlaps with attention latency) --
    {
        const float4* srcH = (const float4*)g_Wp[3][0];
        const float4* srcL = (const float4*)g_Wp[3][1];
#pragma unroll
        for (int i = tid; i < 2048; i += 256) {
            int row = i >> 5;
            int c4  = i & 31;
            *(float4*)&sw[row*WROW + c4*4]        = srcH[i];
            *(float4*)&sw[8704 + row*WROW + c4*4] = srcL[i];
        }
    }

    // ---- attention: each warp handles 8 consecutive buckets ----
    int* wmem = mb + wid * 24;
    for (int b = 0; b < 8; b++) {
        const int r = wid * 8 + b;           // local row 0..63
        const int n = blk * 64 + r;          // bucket id

        int c = min(g_counts[n], CAP_);
        if (lane < c) wmem[lane] = g_members[n*CAP_ + lane];
        __syncwarp();
        if (lane == 0 && c > 1) {            // deterministic order
            for (int i = 1; i < c; i++) {
                int key = wmem[i]; int j = i - 1;
                while (j >= 0 && wmem[j] > key) { wmem[j+1] = wmem[j]; j--; }
                wmem[j+1] = key;
            }
        }
        __syncwarp();

        const int s = n & (S_ - 1);
        float4 q = *(const float4*)&g_Q[s*E_ + lane*4];

        const float* klast = ign ? g_Kfake : &g_Kon[n * E_];
        const float* vlast = ign ? g_Vfake : &g_Von[n * E_];

        float m = -INFINITY, lsum = 0.f;
        float4 acc = make_float4(0.f, 0.f, 0.f, 0.f);

        const float* kr = (c > 0) ? &g_Koff[(size_t)wmem[0] * E_] : klast;
        const float* vr = (c > 0) ? &g_Voff[(size_t)wmem[0] * E_] : vlast;
        float4 kk = *(const float4*)&kr[lane*4];
        float4 vv = *(const float4*)&vr[lane*4];

        for (int p = 0; p <= c; p++) {
            float4 kc = kk, vc = vv;
            if (p < c) {
                const float *kn, *vn;
                if (p + 1 < c) {
                    int t = wmem[p+1];
                    kn = &g_Koff[(size_t)t * E_];
                    vn = &g_Voff[(size_t)t * E_];
                } else {
                    kn = klast; vn = vlast;
                }
                kk = *(const float4*)&kn[lane*4];
                vv = *(const float4*)&vn[lane*4];
            }
            float d = q.x*kc.x + q.y*kc.y + q.z*kc.z + q.w*kc.w;
            d += __shfl_xor_sync(0xffffffffu, d, 1);
            d += __shfl_xor_sync(0xffffffffu, d, 2);   // head-group sum
            float sc = d * 0.25f;                      // 1/sqrt(DH=16)
            float mn = fmaxf(m, sc);
            float corr = expf(m - mn);
            float w = expf(sc - mn);
            lsum = lsum * corr + w;
            acc.x = acc.x*corr + w*vc.x;
            acc.y = acc.y*corr + w*vc.y;
            acc.z = acc.z*corr + w*vc.z;
            acc.w = acc.w*corr + w*vc.w;
            m = mn;
        }
        float inv = 1.0f / lsum;
        *(float4*)&As[r * AROW + lane*4] =
            make_float4(acc.x*inv, acc.y*inv, acc.z*inv, acc.w*inv);
        __syncwarp();
    }
    __syncthreads();

    // ---- GEMM: out[64,128] = As @ Wo (A read from smem) ----
    const int m0 = (wid & 3) * 16;
    const int n0 = (wid >> 2) * 64;
    const int g = lane >> 2;
    const int c = lane & 3;
    float* C = out + (size_t)blk * 64 * E_;

    float acc[8][4];
#pragma unroll
    for (int i = 0; i < 8; i++)
#pragma unroll
        for (int j = 0; j < 4; j++) acc[i][j] = 0.f;

#pragma unroll
    for (int kc = 0; kc < 8; kc++) {
        const int k0 = kc * 16;
        const float* ar = &As[(m0 + g) * AROW + k0 + 2*c];
        float2 x0 = *(const float2*)ar;
        float2 x1 = *(const float2*)(ar + 8*AROW);
        float2 x2 = *(const float2*)(ar + 8);
        float2 x3 = *(const float2*)(ar + 8*AROW + 8);
        uint32_t ah[4], al[4];
        ah[0] = pk2(x0.x, x0.y);  al[0] = pk2(resid(x0.x), resid(x0.y));
        ah[1] = pk2(x1.x, x1.y);  al[1] = pk2(resid(x1.x), resid(x1.y));
        ah[2] = pk2(x2.x, x2.y);  al[2] = pk2(resid(x2.x), resid(x2.y));
        ah[3] = pk2(x3.x, x3.y);  al[3] = pk2(resid(x3.x), resid(x3.y));

        const int brow = kc * 8 + c;
#pragma unroll
        for (int nt = 0; nt < 8; nt++) {
            int col = n0 + nt*8 + g;
            uint32_t bh0 = sw[brow*WROW + col];
            uint32_t bh1 = sw[(brow+4)*WROW + col];
            uint32_t bl0 = sw[8704 + brow*WROW + col];
            uint32_t bl1 = sw[8704 + (brow+4)*WROW + col];
            mma16816(acc[nt], ah, bh0, bh1);
            mma16816(acc[nt], ah, bl0, bl1);
            mma16816(acc[nt], al, bh0, bh1);
        }
    }

#pragma unroll
    for (int nt = 0; nt < 8; nt++) {
        int colb = n0 + nt*8 + 2*c;
        *(float2*)&C[(m0 + g) * E_ + colb]     = make_float2(acc[nt][0], acc[nt][1]);
        *(float2*)&C[(m0 + g + 8) * E_ + colb] = make_float2(acc[nt][2], acc[nt][3]);
    }
}

// ---------------- launcher ---------------------------------------------------
extern "C" void kernel_launch(void* const* d_in, const int* in_sizes, int n_in,
                              void* d_out, int out_size) {
    const float* xoff = (const float*)d_in[0];
    const float* xon  = (const float*)d_in[1];
    const float* zoff = (const float*)d_in[2];
    const float* zon  = (const float*)d_in[3];
    const float* lat  = (const float*)d_in[4];
    const float* fake = (const float*)d_in[5];
    const float* Wq   = (const float*)d_in[6];
    const float* Wk   = (const float*)d_in[7];
    const float* Wv   = (const float*)d_in[8];
    const float* Wo   = (const float*)d_in[9];
    const int*   ign  = (const int*)d_in[10];
    float* out = (float*)d_out;

    int* pCounts;
    cudaGetSymbolAddress((void**)&pCounts, g_counts);

    cudaFuncSetAttribute(gemm_mma,
                         cudaFuncAttributeMaxDynamicSharedMemorySize, W_BYTES);
    cudaFuncSetAttribute(fused_attn_wo,
                         cudaFuncAttributeMaxDynamicSharedMemorySize, FUSED_SMEM);

    cudaMemsetAsync(pCounts, 0, NB_ * sizeof(int));
    // fused prep: weight split (4) + bucketize (128) + fake proj (8)
    prep_kernel<<<140, 256>>>(Wq, Wk, Wv, Wo, xoff, xon, fake);

    // fused K/V/Q projections: 1600 CTAs of 64 rows each
    gemm_mma<<<1600, 256, W_BYTES>>>(zoff, zon, lat);

    // fused attention + output projection: 256 CTAs x 64 buckets
    fused_attn_wo<<<256, 256, FUSED_SMEM>>>(ign, out);
}

// round 9
// speedup vs baseline: 1.1349x; 1.1349x over previous
#include <cuda_runtime.h>
#include <cuda_bf16.h>
#include <math.h>
#include <stdint.h>

// Problem constants
#define B_   4
#define U_   8192
#define E_   128
#define GH_  64
#define GW_  64
#define S_   (GH_*GW_)        // 4096
#define NB_  (B_*S_)          // 16384 buckets
#define NOFF (B_*U_)          // 32768 off-grid tokens
#define CAP_ 23               // MAX_PATCH-1 usable slots

// ---------------- scratch (device globals; no cudaMalloc allowed) ----------
__device__ float g_Koff[NOFF*E_];   // 16 MB
__device__ float g_Voff[NOFF*E_];   // 16 MB
__device__ float g_Kon [NB_*E_];    // 8 MB
__device__ float g_Von [NB_*E_];    // 8 MB
__device__ float g_Q   [S_*E_];     // 2 MB (shared across batch)
__device__ float g_attn[NB_*E_];    // 8 MB
__device__ int   g_counts[NB_];
__device__ int   g_members[NB_*CAP_];
__device__ float g_Kfake[E_];
__device__ float g_Vfake[E_];
// Pre-split bf16 weights, transposed + k-pair-packed for the mma B fragment:
// g_Wp[w][p][kk*128 + n] = bf16(W[2kk][n]) | bf16(W[2kk+1][n])<<16
// w: 0=Wq 1=Wk 2=Wv 3=Wo ; p: 0=hi 1=lo(residual)
__device__ uint32_t g_Wp[4][2][64*128];

// ---------------- helpers ----------------------------------------------------
__device__ __forceinline__ uint32_t pk2(float x, float y) {
    uint32_t lo = (uint32_t)__bfloat16_as_ushort(__float2bfloat16(x));
    uint32_t hi = (uint32_t)__bfloat16_as_ushort(__float2bfloat16(y));
    return lo | (hi << 16);
}
__device__ __forceinline__ float resid(float x) {
    return x - __bfloat162float(__float2bfloat16(x));
}
__device__ __forceinline__ void mma16816(float* c, const uint32_t* a,
                                         uint32_t b0, uint32_t b1) {
    asm volatile(
        "mma.sync.aligned.m16n8k16.row.col.f32.bf16.bf16.f32 "
        "{%0,%1,%2,%3}, {%4,%5,%6,%7}, {%8,%9}, {%0,%1,%2,%3};"
        : "+f"(c[0]), "+f"(c[1]), "+f"(c[2]), "+f"(c[3])
        : "r"(a[0]), "r"(a[1]), "r"(a[2]), "r"(a[3]), "r"(b0), "r"(b1));
}

#define WROW 136
#define SM_WORDS (2 * 64 * WROW)          // 17408 u32 = 69632 B
#define W_BYTES (SM_WORDS * 4)            // 69632

// ---------------- Stage 0: wide weight split (64 CTAs, coalesced) -----------
__global__ void __launch_bounds__(256) wsplit_kernel(const float* __restrict__ Wq,
                                                     const float* __restrict__ Wk,
                                                     const float* __restrict__ Wv,
                                                     const float* __restrict__ Wo) {
    const int wsel  = blockIdx.x >> 4;          // 0..3
    const int chunk = blockIdx.x & 15;          // 0..15
    const float* W = (wsel == 0) ? Wq : (wsel == 1) ? Wk : (wsel == 2) ? Wv : Wo;
    uint32_t* dh = g_Wp[wsel][0];
    uint32_t* dl = g_Wp[wsel][1];
#pragma unroll
    for (int r = 0; r < 2; r++) {
        int idx = chunk * 512 + r * 256 + threadIdx.x;   // 0..8191
        int kk = idx >> 7;
        int n  = idx & 127;
        float w0 = W[(2*kk)   * 128 + n];
        float w1 = W[(2*kk+1) * 128 + n];
        dh[idx] = pk2(w0, w1);
        dl[idx] = pk2(resid(w0), resid(w1));
    }
}

// ---------------- Stage 1: fused bucket + fake-proj + K/V/Q GEMM ------------
// blocks 0..127   : bucket assignment
// blocks 128..135 : fake-embedding projection
// blocks 136..1735: bf16-split HMMA GEMM, one 64x128 tile each
__global__ void __launch_bounds__(256, 3) gemm_mma(const float* __restrict__ zoff,
                                                   const float* __restrict__ zon,
                                                   const float* __restrict__ lat,
                                                   const float* __restrict__ xoff,
                                                   const float* __restrict__ xon,
                                                   const float* __restrict__ fake,
                                                   const float* __restrict__ Wk,
                                                   const float* __restrict__ Wv) {
    extern __shared__ uint32_t sw[];       // [0..8703]=hi, [8704..]=lo
    const int tid = threadIdx.x;
    const int blk = blockIdx.x;

    if (blk < 128) {
        // ---- bucket assignment ----
        int i = blk * 256 + tid;
        float ay0 = xon[0];
        float ay1 = xon[2*GW_];
        float ax0 = xon[1];
        float ax1 = xon[3];
        float x0 = xoff[2*i+0];
        float x1 = xoff[2*i+1];
        float r0 = rintf(__fdiv_rn(x0 - ay0, ay1 - ay0));
        float r1 = rintf(__fdiv_rn(x1 - ax0, ax1 - ax0));
        int i0 = (int)fminf(fmaxf(r0, 0.0f), (float)(GH_-1));
        int i1 = (int)fminf(fmaxf(r1, 0.0f), (float)(GW_-1));
        int flat = (i / U_) * S_ + i0 * GW_ + i1;
        int slot = atomicAdd(&g_counts[flat], 1);
        if (slot < CAP_) g_members[flat*CAP_ + slot] = i;
        return;
    }
    if (blk < 136) {
        // ---- fake projection: 8 blocks x 8 warps = 64 warps, 4 outputs each
        const int wid  = tid >> 5;
        const int lane = tid & 31;
        const int fw = (blk - 128) * 8 + wid;      // 0..63
        float f0 = fake[lane];
        float f1 = fake[lane + 32];
        float f2 = fake[lane + 64];
        float f3 = fake[lane + 96];
#pragma unroll
        for (int t = 0; t < 4; t++) {
            int o = fw * 4 + t;                    // 0..255
            int col = o & 127;
            const float* W = (o < 128) ? Wk : Wv;
            float s = f0 * W[lane*128 + col]
                    + f1 * W[(lane+32)*128 + col]
                    + f2 * W[(lane+64)*128 + col]
                    + f3 * W[(lane+96)*128 + col];
#pragma unroll
            for (int d = 16; d > 0; d >>= 1)
                s += __shfl_xor_sync(0xffffffffu, s, d);
            if (lane == 0) {
                if (o < 128) g_Kfake[col] = s;
                else         g_Vfake[col] = s;
            }
        }
        return;
    }

    // ---- GEMM job decode (64 rows per CTA) ----
    const int jb = blk - 136;                      // 0..1599
    int wsel;
    const float* A;
    float* C;
    if (jb < 512) {
        wsel = 1; A = zoff + (size_t)jb * 64 * E_;        C = g_Koff + (size_t)jb * 64 * E_;
    } else if (jb < 1024) {
        wsel = 2; A = zoff + (size_t)(jb-512) * 64 * E_;  C = g_Voff + (size_t)(jb-512) * 64 * E_;
    } else if (jb < 1280) {
        wsel = 1; A = zon + (size_t)(jb-1024) * 64 * E_;  C = g_Kon + (size_t)(jb-1024) * 64 * E_;
    } else if (jb < 1536) {
        wsel = 2; A = zon + (size_t)(jb-1280) * 64 * E_;  C = g_Von + (size_t)(jb-1280) * 64 * E_;
    } else {
        wsel = 0; A = lat + (size_t)(jb-1536) * 64 * E_;  C = g_Q + (size_t)(jb-1536) * 64 * E_;
    }

    // ---- load packed W hi/lo into padded smem ----
    {
        const float4* srcH = (const float4*)g_Wp[wsel][0];
        const float4* srcL = (const float4*)g_Wp[wsel][1];
#pragma unroll
        for (int i = tid; i < 2048; i += 256) {
            int row = i >> 5;
            int c4  = i & 31;
            *(float4*)&sw[row*WROW + c4*4]        = srcH[i];
            *(float4*)&sw[8704 + row*WROW + c4*4] = srcL[i];
        }
    }
    __syncthreads();

    // ---- warp tiling: 8 warps = 4 (M) x 2 (N); warp tile 16x64 ----
    const int wid  = tid >> 5;
    const int lane = tid & 31;
    const int m0 = (wid & 3) * 16;
    const int n0 = (wid >> 2) * 64;
    const int g = lane >> 2;             // 0..7
    const int c = lane & 3;              // 0..3

    float acc[8][4];
#pragma unroll
    for (int i = 0; i < 8; i++)
#pragma unroll
        for (int j = 0; j < 4; j++) acc[i][j] = 0.f;

    const float* ar = A + (m0 + g) * E_ + 2*c;
    float2 x0 = *(const float2*)ar;
    float2 x1 = *(const float2*)(ar + 8*E_);
    float2 x2 = *(const float2*)(ar + 8);
    float2 x3 = *(const float2*)(ar + 8*E_ + 8);

#pragma unroll
    for (int kc = 0; kc < 8; kc++) {
        float2 y0, y1, y2, y3;
        if (kc < 7) {                       // depth-1 prefetch of next chunk
            const float* an = ar + (kc+1)*16;
            y0 = *(const float2*)an;
            y1 = *(const float2*)(an + 8*E_);
            y2 = *(const float2*)(an + 8);
            y3 = *(const float2*)(an + 8*E_ + 8);
        }
        uint32_t ah[4], al[4];
        ah[0] = pk2(x0.x, x0.y);  al[0] = pk2(resid(x0.x), resid(x0.y));
        ah[1] = pk2(x1.x, x1.y);  al[1] = pk2(resid(x1.x), resid(x1.y));
        ah[2] = pk2(x2.x, x2.y);  al[2] = pk2(resid(x2.x), resid(x2.y));
        ah[3] = pk2(x3.x, x3.y);  al[3] = pk2(resid(x3.x), resid(x3.y));

        const int brow = kc * 8 + c;
#pragma unroll
        for (int nt = 0; nt < 8; nt++) {
            int col = n0 + nt*8 + g;
            uint32_t bh0 = sw[brow*WROW + col];
            uint32_t bh1 = sw[(brow+4)*WROW + col];
            uint32_t bl0 = sw[8704 + brow*WROW + col];
            uint32_t bl1 = sw[8704 + (brow+4)*WROW + col];
            mma16816(acc[nt], ah, bh0, bh1);
            mma16816(acc[nt], ah, bl0, bl1);
            mma16816(acc[nt], al, bh0, bh1);
        }
        if (kc < 7) { x0 = y0; x1 = y1; x2 = y2; x3 = y3; }
    }

    // ---- epilogue ----
#pragma unroll
    for (int nt = 0; nt < 8; nt++) {
        int colb = n0 + nt*8 + 2*c;
        *(float2*)&C[(m0 + g) * E_ + colb]     = make_float2(acc[nt][0], acc[nt][1]);
        *(float2*)&C[(m0 + g + 8) * E_ + colb] = make_float2(acc[nt][2], acc[nt][3]);
    }
}

// ---------------- Stage 2: per-bucket attention (1 warp / bucket) -----------
__global__ void __launch_bounds__(128) attn_kernel(const int* __restrict__ ign_p) {
    __shared__ int mem[4][CAP_];
    const int warp = threadIdx.x >> 5;
    const int lane = threadIdx.x & 31;
    const int n = blockIdx.x * 4 + warp;
    const int ign = *ign_p;

    int c = min(g_counts[n], CAP_);
    if (lane < c) mem[warp][lane] = g_members[n*CAP_ + lane];
    __syncwarp();
    if (lane == 0 && c > 1) {           // deterministic order
        int* a = mem[warp];
        for (int i = 1; i < c; i++) {
            int key = a[i]; int j = i - 1;
            while (j >= 0 && a[j] > key) { a[j+1] = a[j]; j--; }
            a[j+1] = key;
        }
    }
    __syncwarp();

    const int s = n & (S_ - 1);
    float4 q = *(const float4*)&g_Q[s*E_ + lane*4];

    const float* klast = ign ? g_Kfake : &g_Kon[n * E_];
    const float* vlast = ign ? g_Vfake : &g_Von[n * E_];

    float m = -INFINITY, lsum = 0.f;
    float4 acc = make_float4(0.f, 0.f, 0.f, 0.f);

    // depth-1 prefetch of K/V rows
    const float* kr = (c > 0) ? &g_Koff[(size_t)mem[warp][0] * E_] : klast;
    const float* vr = (c > 0) ? &g_Voff[(size_t)mem[warp][0] * E_] : vlast;
    float4 kk = *(const float4*)&kr[lane*4];
    float4 vv = *(const float4*)&vr[lane*4];

    for (int p = 0; p <= c; p++) {
        float4 kc = kk, vc = vv;
        if (p < c) {
            const float *kn, *vn;
            if (p + 1 < c) {
                int t = mem[warp][p+1];
                kn = &g_Koff[(size_t)t * E_];
                vn = &g_Voff[(size_t)t * E_];
            } else {
                kn = klast; vn = vlast;
            }
            kk = *(const float4*)&kn[lane*4];
            vv = *(const float4*)&vn[lane*4];
        }
        float d = q.x*kc.x + q.y*kc.y + q.z*kc.z + q.w*kc.w;
        d += __shfl_xor_sync(0xffffffffu, d, 1);
        d += __shfl_xor_sync(0xffffffffu, d, 2);   // head-group (4 lanes) sum
        float sc = d * 0.25f;                      // 1/sqrt(DH=16)
        float mn = fmaxf(m, sc);
        float corr = expf(m - mn);
        float w = expf(sc - mn);
        lsum = lsum * corr + w;
        acc.x = acc.x*corr + w*vc.x;
        acc.y = acc.y*corr + w*vc.y;
        acc.z = acc.z*corr + w*vc.z;
        acc.w = acc.w*corr + w*vc.w;
        m = mn;
    }
    float inv = 1.0f / lsum;
    float4 o = make_float4(acc.x*inv, acc.y*inv, acc.z*inv, acc.w*inv);
    *(float4*)&g_attn[n*E_ + lane*4] = o;
}

// ---------------- Stage 3: Wo projection (grid 256, 1 tile / CTA) -----------
__global__ void __launch_bounds__(256, 3) wo_gemm(const float* __restrict__ attnA,
                                                  float* __restrict__ outC) {
    extern __shared__ uint32_t sw[];
    const int tid = threadIdx.x;
    const float* A = attnA + (size_t)blockIdx.x * 64 * E_;
    float* C = outC + (size_t)blockIdx.x * 64 * E_;

    {
        const float4* srcH = (const float4*)g_Wp[3][0];
        const float4* srcL = (const float4*)g_Wp[3][1];
#pragma unroll
        for (int i = tid; i < 2048; i += 256) {
            int row = i >> 5;
            int c4  = i & 31;
            *(float4*)&sw[row*WROW + c4*4]        = srcH[i];
            *(float4*)&sw[8704 + row*WROW + c4*4] = srcL[i];
        }
    }
    __syncthreads();

    const int wid  = tid >> 5;
    const int lane = tid & 31;
    const int m0 = (wid & 3) * 16;
    const int n0 = (wid >> 2) * 64;
    const int g = lane >> 2;
    const int c = lane & 3;

    float acc[8][4];
#pragma unroll
    for (int i = 0; i < 8; i++)
#pragma unroll
        for (int j = 0; j < 4; j++) acc[i][j] = 0.f;

    const float* ar = A + (m0 + g) * E_ + 2*c;
    float2 x0 = *(const float2*)ar;
    float2 x1 = *(const float2*)(ar + 8*E_);
    float2 x2 = *(const float2*)(ar + 8);
    float2 x3 = *(const float2*)(ar + 8*E_ + 8);

#pragma unroll
    for (int kc = 0; kc < 8; kc++) {
        float2 y0, y1, y2, y3;
        if (kc < 7) {
            const float* an = ar + (kc+1)*16;
            y0 = *(const float2*)an;
            y1 = *(const float2*)(an + 8*E_);
            y2 = *(const float2*)(an + 8);
            y3 = *(const float2*)(an + 8*E_ + 8);
        }
        uint32_t ah[4], al[4];
        ah[0] = pk2(x0.x, x0.y);  al[0] = pk2(resid(x0.x), resid(x0.y));
        ah[1] = pk2(x1.x, x1.y);  al[1] = pk2(resid(x1.x), resid(x1.y));
        ah[2] = pk2(x2.x, x2.y);  al[2] = pk2(resid(x2.x), resid(x2.y));
        ah[3] = pk2(x3.x, x3.y);  al[3] = pk2(resid(x3.x), resid(x3.y));

        const int brow = kc * 8 + c;
#pragma unroll
        for (int nt = 0; nt < 8; nt++) {
            int col = n0 + nt*8 + g;
            uint32_t bh0 = sw[brow*WROW + col];
            uint32_t bh1 = sw[(brow+4)*WROW + col];
            uint32_t bl0 = sw[8704 + brow*WROW + col];
            uint32_t bl1 = sw[8704 + (brow+4)*WROW + col];
            mma16816(acc[nt], ah, bh0, bh1);
            mma16816(acc[nt], ah, bl0, bl1);
            mma16816(acc[nt], al, bh0, bh1);
        }
        if (kc < 7) { x0 = y0; x1 = y1; x2 = y2; x3 = y3; }
    }

#pragma unroll
    for (int nt = 0; nt < 8; nt++) {
        int colb = n0 + nt*8 + 2*c;
        *(float2*)&C[(m0 + g) * E_ + colb]     = make_float2(acc[nt][0], acc[nt][1]);
        *(float2*)&C[(m0 + g + 8) * E_ + colb] = make_float2(acc[nt][2], acc[nt][3]);
    }
}

// ---------------- launcher ---------------------------------------------------
extern "C" void kernel_launch(void* const* d_in, const int* in_sizes, int n_in,
                              void* d_out, int out_size) {
    const float* xoff = (const float*)d_in[0];
    const float* xon  = (const float*)d_in[1];
    const float* zoff = (const float*)d_in[2];
    const float* zon  = (const float*)d_in[3];
    const float* lat  = (const float*)d_in[4];
    const float* fake = (const float*)d_in[5];
    const float* Wq   = (const float*)d_in[6];
    const float* Wk   = (const float*)d_in[7];
    const float* Wv   = (const float*)d_in[8];
    const float* Wo   = (const float*)d_in[9];
    const int*   ign  = (const int*)d_in[10];
    float* out = (float*)d_out;

    float* pAttn;
    int* pCounts;
    cudaGetSymbolAddress((void**)&pAttn, g_attn);
    cudaGetSymbolAddress((void**)&pCounts, g_counts);

    cudaFuncSetAttribute(gemm_mma,
                         cudaFuncAttributeMaxDynamicSharedMemorySize, W_BYTES);
    cudaFuncSetAttribute(wo_gemm,
                         cudaFuncAttributeMaxDynamicSharedMemorySize, W_BYTES);

    cudaMemsetAsync(pCounts, 0, NB_ * sizeof(int));
    // wide weight split: 64 CTAs, fully coalesced
    wsplit_kernel<<<64, 256>>>(Wq, Wk, Wv, Wo);

    // fused bucket(128) + fake(8) + K/V/Q GEMM(1600)
    gemm_mma<<<1736, 256, W_BYTES>>>(zoff, zon, lat, xoff, xon, fake, Wk, Wv);

    attn_kernel<<<NB_ / 4, 128>>>(ign);

    // output projection
    wo_gemm<<<256, 256, W_BYTES>>>(pAttn, out);
}

// round 11
// speedup vs baseline: 1.2038x; 1.0607x over previous
#include <cuda_runtime.h>
#include <cuda_fp16.h>
#include <math.h>
#include <stdint.h>

// Problem constants
#define B_   4
#define U_   8192
#define E_   128
#define GH_  64
#define GW_  64
#define S_   (GH_*GW_)        // 4096
#define NB_  (B_*S_)          // 16384 buckets
#define NOFF (B_*U_)          // 32768 off-grid tokens
#define CAP_ 23               // MAX_PATCH-1 usable slots

// ---------------- scratch (device globals; no cudaMalloc allowed) ----------
__device__ float g_Koff[NOFF*E_];   // 16 MB
__device__ float g_Voff[NOFF*E_];   // 16 MB
__device__ float g_Kon [NB_*E_];    // 8 MB
__device__ float g_Von [NB_*E_];    // 8 MB
__device__ float g_Q   [S_*E_];     // 2 MB (shared across batch)
__device__ float g_attn[NB_*E_];    // 8 MB
__device__ int   g_counts[NB_];
__device__ int   g_members[NB_*CAP_];
__device__ float g_Kfake[E_];
__device__ float g_Vfake[E_];
// Pre-split fp16 weights, transposed + k-pair-packed for the mma B fragment:
// g_Wp[w][p][kk*128 + n] = fp16(W[2kk][n]) | fp16(W[2kk+1][n])<<16
// w: 0=Wq 1=Wk 2=Wv 3=Wo ; p: 0=hi 1=residual
__device__ uint32_t g_Wp[4][2][64*128];

// ---------------- helpers ----------------------------------------------------
__device__ __forceinline__ uint32_t pk2h(float x, float y) {
    __half2 h = __floats2half2_rn(x, y);
    return *reinterpret_cast<uint32_t*>(&h);
}
__device__ __forceinline__ float residh(float x) {
    return x - __half2float(__float2half_rn(x));
}
__device__ __forceinline__ void mma16816(float* c, const uint32_t* a,
                                         uint32_t b0, uint32_t b1) {
    asm volatile(
        "mma.sync.aligned.m16n8k16.row.col.f32.f16.f16.f32 "
        "{%0,%1,%2,%3}, {%4,%5,%6,%7}, {%8,%9}, {%0,%1,%2,%3};"
        : "+f"(c[0]), "+f"(c[1]), "+f"(c[2]), "+f"(c[3])
        : "r"(a[0]), "r"(a[1]), "r"(a[2]), "r"(a[3]), "r"(b0), "r"(b1));
}

#define WROW 136
#define W_BYTES   (2 * 64 * WROW * 4)     // hi+lo: 69632 B (3-pass kernels)
#define WH_BYTES  (64 * WROW * 4)         // hi only: 34816 B (2-pass wo_gemm)

// ---------------- Stage 0: wide weight split (64 CTAs, coalesced) -----------
__global__ void __launch_bounds__(256) wsplit_kernel(const float* __restrict__ Wq,
                                                     const float* __restrict__ Wk,
                                                     const float* __restrict__ Wv,
                                                     const float* __restrict__ Wo) {
    const int wsel  = blockIdx.x >> 4;          // 0..3
    const int chunk = blockIdx.x & 15;          // 0..15
    const float* W = (wsel == 0) ? Wq : (wsel == 1) ? Wk : (wsel == 2) ? Wv : Wo;
    uint32_t* dh = g_Wp[wsel][0];
    uint32_t* dl = g_Wp[wsel][1];
#pragma unroll
    for (int r = 0; r < 2; r++) {
        int idx = chunk * 512 + r * 256 + threadIdx.x;   // 0..8191
        int kk = idx >> 7;
        int n  = idx & 127;
        float w0 = W[(2*kk)   * 128 + n];
        float w1 = W[(2*kk+1) * 128 + n];
        dh[idx] = pk2h(w0, w1);
        dl[idx] = pk2h(residh(w0), residh(w1));
    }
}

// ---------------- Stage 1: fused bucket + fake-proj + K/V/Q GEMM ------------
// blocks 0..127   : bucket assignment
// blocks 128..135 : fake-embedding projection (fp32, exact)
// blocks 136..1735: fp16-split HMMA GEMM, one 64x128 tile each
//   K/Q tiles: 3-pass (Ah*Wh + Ah*Wl + Al*Wh), error ~2^-21
//   V tiles:   2-pass (Ah*Wh + Al*Wh), W single fp16, error ~2^-12 (linear path)
__global__ void __launch_bounds__(256, 3) gemm_mma(const float* __restrict__ zoff,
                                                   const float* __restrict__ zon,
                                                   const float* __restrict__ lat,
                                                   const float* __restrict__ xoff,
                                                   const float* __restrict__ xon,
                                                   const float* __restrict__ fake,
                                                   const float* __restrict__ Wk,
                                                   const float* __restrict__ Wv) {
    extern __shared__ uint32_t sw[];       // [0..8703]=hi, [8704..]=lo (3-pass only)
    const int tid = threadIdx.x;
    const int blk = blockIdx.x;

    if (blk < 128) {
        // ---- bucket assignment ----
        int i = blk * 256 + tid;
        float ay0 = xon[0];
        float ay1 = xon[2*GW_];
        float ax0 = xon[1];
        float ax1 = xon[3];
        float x0 = xoff[2*i+0];
        float x1 = xoff[2*i+1];
        float r0 = rintf(__fdiv_rn(x0 - ay0, ay1 - ay0));
        float r1 = rintf(__fdiv_rn(x1 - ax0, ax1 - ax0));
        int i0 = (int)fminf(fmaxf(r0, 0.0f), (float)(GH_-1));
        int i1 = (int)fminf(fmaxf(r1, 0.0f), (float)(GW_-1));
        int flat = (i / U_) * S_ + i0 * GW_ + i1;
        int slot = atomicAdd(&g_counts[flat], 1);
        if (slot < CAP_) g_members[flat*CAP_ + slot] = i;
        return;
    }
    if (blk < 136) {
        // ---- fake projection: 8 blocks x 8 warps = 64 warps, 4 outputs each
        const int wid  = tid >> 5;
        const int lane = tid & 31;
        const int fw = (blk - 128) * 8 + wid;      // 0..63
        float f0 = fake[lane];
        float f1 = fake[lane + 32];
        float f2 = fake[lane + 64];
        float f3 = fake[lane + 96];
#pragma unroll
        for (int t = 0; t < 4; t++) {
            int o = fw * 4 + t;                    // 0..255
            int col = o & 127;
            const float* W = (o < 128) ? Wk : Wv;
            float s = f0 * W[lane*128 + col]
                    + f1 * W[(lane+32)*128 + col]
                    + f2 * W[(lane+64)*128 + col]
                    + f3 * W[(lane+96)*128 + col];
#pragma unroll
            for (int d = 16; d > 0; d >>= 1)
                s += __shfl_xor_sync(0xffffffffu, s, d);
            if (lane == 0) {
                if (o < 128) g_Kfake[col] = s;
                else         g_Vfake[col] = s;
            }
        }
        return;
    }

    // ---- GEMM job decode (64 rows per CTA) ----
    const int jb = blk - 136;                      // 0..1599
    int wsel;
    const float* A;
    float* C;
    if (jb < 512) {
        wsel = 1; A = zoff + (size_t)jb * 64 * E_;        C = g_Koff + (size_t)jb * 64 * E_;
    } else if (jb < 1024) {
        wsel = 2; A = zoff + (size_t)(jb-512) * 64 * E_;  C = g_Voff + (size_t)(jb-512) * 64 * E_;
    } else if (jb < 1280) {
        wsel = 1; A = zon + (size_t)(jb-1024) * 64 * E_;  C = g_Kon + (size_t)(jb-1024) * 64 * E_;
    } else if (jb < 1536) {
        wsel = 2; A = zon + (size_t)(jb-1280) * 64 * E_;  C = g_Von + (size_t)(jb-1280) * 64 * E_;
    } else {
        wsel = 0; A = lat + (size_t)(jb-1536) * 64 * E_;  C = g_Q + (size_t)(jb-1536) * 64 * E_;
    }
    const bool twopass = (wsel == 2);              // V tiles

    // ---- load packed W hi (and lo for 3-pass) into padded smem ----
    // Each matrix = 8192 u32 = 2048 float4; smem row = 128 u32 = 32 float4.
    {
        const float4* srcH = (const float4*)g_Wp[wsel][0];
#pragma unroll
        for (int i = tid; i < 2048; i += 256) {
            int row = i >> 5;            // 0..63
            int c4  = i & 31;            // float4 within row
            *(float4*)&sw[row*WROW + c4*4] = srcH[i];
        }
        if (!twopass) {
            const float4* srcL = (const float4*)g_Wp[wsel][1];
#pragma unroll
            for (int i = tid; i < 2048; i += 256) {
                int row = i >> 5;
                int c4  = i & 31;
                *(float4*)&sw[8704 + row*WROW + c4*4] = srcL[i];
            }
        }
    }
    __syncthreads();

    // ---- warp tiling: 8 warps = 4 (M) x 2 (N); warp tile 16x64 ----
    const int wid  = tid >> 5;
    const int lane = tid & 31;
    const int m0 = (wid & 3) * 16;
    const int n0 = (wid >> 2) * 64;
    const int g = lane >> 2;             // 0..7
    const int c = lane & 3;              // 0..3

    float acc[8][4];
#pragma unroll
    for (int i = 0; i < 8; i++)
#pragma unroll
        for (int j = 0; j < 4; j++) acc[i][j] = 0.f;

    const float* ar = A + (m0 + g) * E_ + 2*c;
    float2 x0 = *(const float2*)ar;
    float2 x1 = *(const float2*)(ar + 8*E_);
    float2 x2 = *(const float2*)(ar + 8);
    float2 x3 = *(const float2*)(ar + 8*E_ + 8);

#pragma unroll
    for (int kc = 0; kc < 8; kc++) {
        float2 y0, y1, y2, y3;
        if (kc < 7) {                       // depth-1 prefetch of next chunk
            const float* an = ar + (kc+1)*16;
            y0 = *(const float2*)an;
            y1 = *(const float2*)(an + 8*E_);
            y2 = *(const float2*)(an + 8);
            y3 = *(const float2*)(an + 8*E_ + 8);
        }
        uint32_t ah[4], al[4];
        ah[0] = pk2h(x0.x, x0.y);  al[0] = pk2h(residh(x0.x), residh(x0.y));
        ah[1] = pk2h(x1.x, x1.y);  al[1] = pk2h(residh(x1.x), residh(x1.y));
        ah[2] = pk2h(x2.x, x2.y);  al[2] = pk2h(residh(x2.x), residh(x2.y));
        ah[3] = pk2h(x3.x, x3.y);  al[3] = pk2h(residh(x3.x), residh(x3.y));

        const int brow = kc * 8 + c;
        if (twopass) {
#pragma unroll
            for (int nt = 0; nt < 8; nt++) {
                int col = n0 + nt*8 + g;
                uint32_t bh0 = sw[brow*WROW + col];
                uint32_t bh1 = sw[(brow+4)*WROW + col];
                mma16816(acc[nt], ah, bh0, bh1);
                mma16816(acc[nt], al, bh0, bh1);
            }
        } else {
#pragma unroll
            for (int nt = 0; nt < 8; nt++) {
                int col = n0 + nt*8 + g;
                uint32_t bh0 = sw[brow*WROW + col];
                uint32_t bh1 = sw[(brow+4)*WROW + col];
                uint32_t bl0 = sw[8704 + brow*WROW + col];
                uint32_t bl1 = sw[8704 + (brow+4)*WROW + col];
                mma16816(acc[nt], ah, bh0, bh1);
                mma16816(acc[nt], ah, bl0, bl1);
                mma16816(acc[nt], al, bh0, bh1);
            }
        }
        if (kc < 7) { x0 = y0; x1 = y1; x2 = y2; x3 = y3; }
    }

    // ---- epilogue ----
#pragma unroll
    for (int nt = 0; nt < 8; nt++) {
        int colb = n0 + nt*8 + 2*c;
        *(float2*)&C[(m0 + g) * E_ + colb]     = make_float2(acc[nt][0], acc[nt][1]);
        *(float2*)&C[(m0 + g + 8) * E_ + colb] = make_float2(acc[nt][2], acc[nt][3]);
    }
}

// ---------------- Stage 2: per-bucket attention (1 warp / bucket) -----------
__global__ void __launch_bounds__(128) attn_kernel(const int* __restrict__ ign_p) {
    __shared__ int mem[4][CAP_];
    const int warp = threadIdx.x >> 5;
    const int lane = threadIdx.x & 31;
    const int n = blockIdx.x * 4 + warp;
    const int ign = *ign_p;

    int c = min(g_counts[n], CAP_);
    if (lane < c) mem[warp][lane] = g_members[n*CAP_ + lane];
    __syncwarp();
    if (lane == 0 && c > 1) {           // deterministic order
        int* a = mem[warp];
        for (int i = 1; i < c; i++) {
            int key = a[i]; int j = i - 1;
            while (j >= 0 && a[j] > key) { a[j+1] = a[j]; j--; }
            a[j+1] = key;
        }
    }
    __syncwarp();

    const int s = n & (S_ - 1);
    float4 q = *(const float4*)&g_Q[s*E_ + lane*4];

    const float* klast = ign ? g_Kfake : &g_Kon[n * E_];
    const float* vlast = ign ? g_Vfake : &g_Von[n * E_];

    float m = -INFINITY, lsum = 0.f;
    float4 acc = make_float4(0.f, 0.f, 0.f, 0.f);

    // depth-1 prefetch of K/V rows
    const float* kr = (c > 0) ? &g_Koff[(size_t)mem[warp][0] * E_] : klast;
    const float* vr = (c > 0) ? &g_Voff[(size_t)mem[warp][0] * E_] : vlast;
    float4 kk = *(const float4*)&kr[lane*4];
    float4 vv = *(const float4*)&vr[lane*4];

    for (int p = 0; p <= c; p++) {
        float4 kc = kk, vc = vv;
        if (p < c) {
            const float *kn, *vn;
            if (p + 1 < c) {
                int t = mem[warp][p+1];
                kn = &g_Koff[(size_t)t * E_];
                vn = &g_Voff[(size_t)t * E_];
            } else {
                kn = klast; vn = vlast;
            }
            kk = *(const float4*)&kn[lane*4];
            vv = *(const float4*)&vn[lane*4];
        }
        float d = q.x*kc.x + q.y*kc.y + q.z*kc.z + q.w*kc.w;
        d += __shfl_xor_sync(0xffffffffu, d, 1);
        d += __shfl_xor_sync(0xffffffffu, d, 2);   // head-group (4 lanes) sum
        float sc = d * 0.25f;                      // 1/sqrt(DH=16)
        float mn = fmaxf(m, sc);
        float corr = expf(m - mn);
        float w = expf(sc - mn);
        lsum = lsum * corr + w;
        acc.x = acc.x*corr + w*vc.x;
        acc.y = acc.y*corr + w*vc.y;
        acc.z = acc.z*corr + w*vc.z;
        acc.w = acc.w*corr + w*vc.w;
        m = mn;
    }
    float inv = 1.0f / lsum;
    float4 o = make_float4(acc.x*inv, acc.y*inv, acc.z*inv, acc.w*inv);
    *(float4*)&g_attn[n*E_ + lane*4] = o;
}

// ---------------- Stage 3: Wo projection (2-pass A-split, Wh only) ----------
__global__ void __launch_bounds__(256, 4) wo_gemm(const float* __restrict__ attnA,
                                                  float* __restrict__ outC) {
    extern __shared__ uint32_t sw[];      // hi only: 64 x WROW
    const int tid = threadIdx.x;
    const float* A = attnA + (size_t)blockIdx.x * 64 * E_;
    float* C = outC + (size_t)blockIdx.x * 64 * E_;

    {
        const float4* srcH = (const float4*)g_Wp[3][0];
#pragma unroll
        for (int i = tid; i < 2048; i += 256) {
            int row = i >> 5;            // 0..63
            int c4  = i & 31;            // float4 within row
            *(float4*)&sw[row*WROW + c4*4] = srcH[i];
        }
    }
    __syncthreads();

    const int wid  = tid >> 5;
    const int lane = tid & 31;
    const int m0 = (wid & 3) * 16;
    const int n0 = (wid >> 2) * 64;
    const int g = lane >> 2;
    const int c = lane & 3;

    float acc[8][4];
#pragma unroll
    for (int i = 0; i < 8; i++)
#pragma unroll
        for (int j = 0; j < 4; j++) acc[i][j] = 0.f;

    const float* ar = A + (m0 + g) * E_ + 2*c;
    float2 x0 = *(const float2*)ar;
    float2 x1 = *(const float2*)(ar + 8*E_);
    float2 x2 = *(const float2*)(ar + 8);
    float2 x3 = *(const float2*)(ar + 8*E_ + 8);

#pragma unroll
    for (int kc = 0; kc < 8; kc++) {
        float2 y0, y1, y2, y3;
        if (kc < 7) {
            const float* an = ar + (kc+1)*16;
            y0 = *(const float2*)an;
            y1 = *(const float2*)(an + 8*E_);
            y2 = *(const float2*)(an + 8);
            y3 = *(const float2*)(an + 8*E_ + 8);
        }
        uint32_t ah[4], al[4];
        ah[0] = pk2h(x0.x, x0.y);  al[0] = pk2h(residh(x0.x), residh(x0.y));
        ah[1] = pk2h(x1.x, x1.y);  al[1] = pk2h(residh(x1.x), residh(x1.y));
        ah[2] = pk2h(x2.x, x2.y);  al[2] = pk2h(residh(x2.x), residh(x2.y));
        ah[3] = pk2h(x3.x, x3.y);  al[3] = pk2h(residh(x3.x), residh(x3.y));

        const int brow = kc * 8 + c;
#pragma unroll
        for (int nt = 0; nt < 8; nt++) {
            int col = n0 + nt*8 + g;
            uint32_t bh0 = sw[brow*WROW + col];
            uint32_t bh1 = sw[(brow+4)*WROW + col];
            mma16816(acc[nt], ah, bh0, bh1);
            mma16816(acc[nt], al, bh0, bh1);
        }
        if (kc < 7) { x0 = y0; x1 = y1; x2 = y2; x3 = y3; }
    }

#pragma unroll
    for (int nt = 0; nt < 8; nt++) {
        int colb = n0 + nt*8 + 2*c;
        *(float2*)&C[(m0 + g) * E_ + colb]     = make_float2(acc[nt][0], acc[nt][1]);
        *(float2*)&C[(m0 + g + 8) * E_ + colb] = make_float2(acc[nt][2], acc[nt][3]);
    }
}

// ---------------- launcher ---------------------------------------------------
extern "C" void kernel_launch(void* const* d_in, const int* in_sizes, int n_in,
                              void* d_out, int out_size) {
    const float* xoff = (const float*)d_in[0];
    const float* xon  = (const float*)d_in[1];
    const float* zoff = (const float*)d_in[2];
    const float* zon  = (const float*)d_in[3];
    const float* lat  = (const float*)d_in[4];
    const float* fake = (const float*)d_in[5];
    const float* Wq   = (const float*)d_in[6];
    const float* Wk   = (const float*)d_in[7];
    const float* Wv   = (const float*)d_in[8];
    const float* Wo   = (const float*)d_in[9];
    const int*   ign  = (const int*)d_in[10];
    float* out = (float*)d_out;

    float* pAttn;
    int* pCounts;
    cudaGetSymbolAddress((void**)&pAttn, g_attn);
    cudaGetSymbolAddress((void**)&pCounts, g_counts);

    cudaFuncSetAttribute(gemm_mma,
                         cudaFuncAttributeMaxDynamicSharedMemorySize, W_BYTES);
    cudaFuncSetAttribute(wo_gemm,
                         cudaFuncAttributeMaxDynamicSharedMemorySize, WH_BYTES);

    cudaMemsetAsync(pCounts, 0, NB_ * sizeof(int));
    // wide weight split: 64 CTAs, fully coalesced
    wsplit_kernel<<<64, 256>>>(Wq, Wk, Wv, Wo);

    // fused bucket(128) + fake(8) + K/V/Q GEMM(1600)
    gemm_mma<<<1736, 256, W_BYTES>>>(zoff, zon, lat, xoff, xon, fake, Wk, Wv);

    attn_kernel<<<NB_ / 4, 128>>>(ign);

    // output projection (2-pass fp16)
    wo_gemm<<<256, 256, WH_BYTES>>>(pAttn, out);
}

// round 12
// speedup vs baseline: 1.2670x; 1.0525x over previous
#include <cuda_runtime.h>
#include <cuda_fp16.h>
#include <math.h>
#include <stdint.h>

// Problem constants
#define B_   4
#define U_   8192
#define E_   128
#define GH_  64
#define GW_  64
#define S_   (GH_*GW_)        // 4096
#define NB_  (B_*S_)          // 16384 buckets
#define NOFF (B_*U_)          // 32768 off-grid tokens
#define CAP_ 23               // MAX_PATCH-1 usable slots

// ---------------- scratch (device globals; no cudaMalloc allowed) ----------
__device__ float g_Koff[NOFF*E_];   // 16 MB
__device__ float g_Voff[NOFF*E_];   // 16 MB
__device__ float g_Kon [NB_*E_];    // 8 MB
__device__ float g_Von [NB_*E_];    // 8 MB
__device__ float g_Q   [S_*E_];     // 2 MB (shared across batch)
__device__ float g_attn[NB_*E_];    // 8 MB
__device__ int   g_counts[NB_];
__device__ int   g_members[NB_*CAP_];
__device__ float g_Kfake[E_];
__device__ float g_Vfake[E_];
// Pre-split fp16 weights, transposed + k-pair-packed for the mma B fragment:
// g_Wp[w][p][kk*128 + n] = fp16(W[2kk][n]) | fp16(W[2kk+1][n])<<16
// w: 0=Wq 1=Wk 2=Wv 3=Wo ; p: 0=hi 1=residual
__device__ uint32_t g_Wp[4][2][64*128];

// ---------------- helpers ----------------------------------------------------
__device__ __forceinline__ uint32_t pk2h(float x, float y) {
    __half2 h = __floats2half2_rn(x, y);
    return *reinterpret_cast<uint32_t*>(&h);
}
__device__ __forceinline__ float residh(float x) {
    return x - __half2float(__float2half_rn(x));
}
__device__ __forceinline__ void mma16816(float* c, const uint32_t* a,
                                         uint32_t b0, uint32_t b1) {
    asm volatile(
        "mma.sync.aligned.m16n8k16.row.col.f32.f16.f16.f32 "
        "{%0,%1,%2,%3}, {%4,%5,%6,%7}, {%8,%9}, {%0,%1,%2,%3};"
        : "+f"(c[0]), "+f"(c[1]), "+f"(c[2]), "+f"(c[3])
        : "r"(a[0]), "r"(a[1]), "r"(a[2]), "r"(a[3]), "r"(b0), "r"(b1));
}

#define WROW 136
#define W_BYTES   (2 * 64 * WROW * 4)     // hi+lo: 69632 B (3-pass kernels)
#define WH_BYTES  (64 * WROW * 4)         // hi only: 34816 B (2-pass wo_gemm)

// ---------------- Stage 0: weight split + counts clear (64 CTAs) ------------
__global__ void __launch_bounds__(256) wsplit_kernel(const float* __restrict__ Wq,
                                                     const float* __restrict__ Wk,
                                                     const float* __restrict__ Wv,
                                                     const float* __restrict__ Wo) {
    // clear bucket counts: 64*256 == NB_
    g_counts[blockIdx.x * 256 + threadIdx.x] = 0;

    const int wsel  = blockIdx.x >> 4;          // 0..3
    const int chunk = blockIdx.x & 15;          // 0..15
    const float* W = (wsel == 0) ? Wq : (wsel == 1) ? Wk : (wsel == 2) ? Wv : Wo;
    uint32_t* dh = g_Wp[wsel][0];
    uint32_t* dl = g_Wp[wsel][1];
#pragma unroll
    for (int r = 0; r < 2; r++) {
        int idx = chunk * 512 + r * 256 + threadIdx.x;   // 0..8191
        int kk = idx >> 7;
        int n  = idx & 127;
        float w0 = W[(2*kk)   * 128 + n];
        float w1 = W[(2*kk+1) * 128 + n];
        dh[idx] = pk2h(w0, w1);
        dl[idx] = pk2h(residh(w0), residh(w1));
    }
}

// ---------------- Stage 1: fused bucket + fake-proj + K/V/Q GEMM ------------
// blocks 0..127   : bucket assignment
// blocks 128..135 : fake-embedding projection (fp32, exact)
// blocks 136..1735: fp16-split HMMA GEMM, one 64x128 tile each
//   K/Q tiles: 3-pass (Ah*Wh + Ah*Wl + Al*Wh), error ~2^-21
//   V tiles:   2-pass (Ah*Wh + Al*Wh), W single fp16, error ~2^-12 (linear path)
__global__ void __launch_bounds__(256, 3) gemm_mma(const float* __restrict__ zoff,
                                                   const float* __restrict__ zon,
                                                   const float* __restrict__ lat,
                                                   const float* __restrict__ xoff,
                                                   const float* __restrict__ xon,
                                                   const float* __restrict__ fake,
                                                   const float* __restrict__ Wk,
                                                   const float* __restrict__ Wv) {
    extern __shared__ uint32_t sw[];       // [0..8703]=hi, [8704..]=lo (3-pass only)
    const int tid = threadIdx.x;
    const int blk = blockIdx.x;

    if (blk < 128) {
        // ---- bucket assignment ----
        int i = blk * 256 + tid;
        float ay0 = xon[0];
        float ay1 = xon[2*GW_];
        float ax0 = xon[1];
        float ax1 = xon[3];
        float x0 = xoff[2*i+0];
        float x1 = xoff[2*i+1];
        float r0 = rintf(__fdiv_rn(x0 - ay0, ay1 - ay0));
        float r1 = rintf(__fdiv_rn(x1 - ax0, ax1 - ax0));
        int i0 = (int)fminf(fmaxf(r0, 0.0f), (float)(GH_-1));
        int i1 = (int)fminf(fmaxf(r1, 0.0f), (float)(GW_-1));
        int flat = (i / U_) * S_ + i0 * GW_ + i1;
        int slot = atomicAdd(&g_counts[flat], 1);
        if (slot < CAP_) g_members[flat*CAP_ + slot] = i;
        return;
    }
    if (blk < 136) {
        // ---- fake projection: 8 blocks x 8 warps = 64 warps, 4 outputs each
        const int wid  = tid >> 5;
        const int lane = tid & 31;
        const int fw = (blk - 128) * 8 + wid;      // 0..63
        float f0 = fake[lane];
        float f1 = fake[lane + 32];
        float f2 = fake[lane + 64];
        float f3 = fake[lane + 96];
#pragma unroll
        for (int t = 0; t < 4; t++) {
            int o = fw * 4 + t;                    // 0..255
            int col = o & 127;
            const float* W = (o < 128) ? Wk : Wv;
            float s = f0 * W[lane*128 + col]
                    + f1 * W[(lane+32)*128 + col]
                    + f2 * W[(lane+64)*128 + col]
                    + f3 * W[(lane+96)*128 + col];
#pragma unroll
            for (int d = 16; d > 0; d >>= 1)
                s += __shfl_xor_sync(0xffffffffu, s, d);
            if (lane == 0) {
                if (o < 128) g_Kfake[col] = s;
                else         g_Vfake[col] = s;
            }
        }
        return;
    }

    // ---- GEMM job decode (64 rows per CTA) ----
    const int jb = blk - 136;                      // 0..1599
    int wsel;
    const float* A;
    float* C;
    if (jb < 512) {
        wsel = 1; A = zoff + (size_t)jb * 64 * E_;        C = g_Koff + (size_t)jb * 64 * E_;
    } else if (jb < 1024) {
        wsel = 2; A = zoff + (size_t)(jb-512) * 64 * E_;  C = g_Voff + (size_t)(jb-512) * 64 * E_;
    } else if (jb < 1280) {
        wsel = 1; A = zon + (size_t)(jb-1024) * 64 * E_;  C = g_Kon + (size_t)(jb-1024) * 64 * E_;
    } else if (jb < 1536) {
        wsel = 2; A = zon + (size_t)(jb-1280) * 64 * E_;  C = g_Von + (size_t)(jb-1280) * 64 * E_;
    } else {
        wsel = 0; A = lat + (size_t)(jb-1536) * 64 * E_;  C = g_Q + (size_t)(jb-1536) * 64 * E_;
    }
    const bool twopass = (wsel == 2);              // V tiles

    // ---- load packed W hi (and lo for 3-pass) into padded smem ----
    {
        const float4* srcH = (const float4*)g_Wp[wsel][0];
#pragma unroll
        for (int i = tid; i < 2048; i += 256) {
            int row = i >> 5;            // 0..63
            int c4  = i & 31;            // float4 within row
            *(float4*)&sw[row*WROW + c4*4] = srcH[i];
        }
        if (!twopass) {
            const float4* srcL = (const float4*)g_Wp[wsel][1];
#pragma unroll
            for (int i = tid; i < 2048; i += 256) {
                int row = i >> 5;
                int c4  = i & 31;
                *(float4*)&sw[8704 + row*WROW + c4*4] = srcL[i];
            }
        }
    }
    __syncthreads();

    // ---- warp tiling: 8 warps = 4 (M) x 2 (N); warp tile 16x64 ----
    const int wid  = tid >> 5;
    const int lane = tid & 31;
    const int m0 = (wid & 3) * 16;
    const int n0 = (wid >> 2) * 64;
    const int g = lane >> 2;             // 0..7
    const int c = lane & 3;              // 0..3

    float acc[8][4];
#pragma unroll
    for (int i = 0; i < 8; i++)
#pragma unroll
        for (int j = 0; j < 4; j++) acc[i][j] = 0.f;

    const float* ar = A + (m0 + g) * E_ + 2*c;
    float2 x0 = *(const float2*)ar;
    float2 x1 = *(const float2*)(ar + 8*E_);
    float2 x2 = *(const float2*)(ar + 8);
    float2 x3 = *(const float2*)(ar + 8*E_ + 8);

#pragma unroll
    for (int kc = 0; kc < 8; kc++) {
        float2 y0, y1, y2, y3;
        if (kc < 7) {                       // depth-1 prefetch of next chunk
            const float* an = ar + (kc+1)*16;
            y0 = *(const float2*)an;
            y1 = *(const float2*)(an + 8*E_);
            y2 = *(const float2*)(an + 8);
            y3 = *(const float2*)(an + 8*E_ + 8);
        }
        uint32_t ah[4], al[4];
        ah[0] = pk2h(x0.x, x0.y);  al[0] = pk2h(residh(x0.x), residh(x0.y));
        ah[1] = pk2h(x1.x, x1.y);  al[1] = pk2h(residh(x1.x), residh(x1.y));
        ah[2] = pk2h(x2.x, x2.y);  al[2] = pk2h(residh(x2.x), residh(x2.y));
        ah[3] = pk2h(x3.x, x3.y);  al[3] = pk2h(residh(x3.x), residh(x3.y));

        const int brow = kc * 8 + c;
        if (twopass) {
#pragma unroll
            for (int nt = 0; nt < 8; nt++) {
                int col = n0 + nt*8 + g;
                uint32_t bh0 = sw[brow*WROW + col];
                uint32_t bh1 = sw[(brow+4)*WROW + col];
                mma16816(acc[nt], ah, bh0, bh1);
                mma16816(acc[nt], al, bh0, bh1);
            }
        } else {
#pragma unroll
            for (int nt = 0; nt < 8; nt++) {
                int col = n0 + nt*8 + g;
                uint32_t bh0 = sw[brow*WROW + col];
                uint32_t bh1 = sw[(brow+4)*WROW + col];
                uint32_t bl0 = sw[8704 + brow*WROW + col];
                uint32_t bl1 = sw[8704 + (brow+4)*WROW + col];
                mma16816(acc[nt], ah, bh0, bh1);
                mma16816(acc[nt], ah, bl0, bl1);
                mma16816(acc[nt], al, bh0, bh1);
            }
        }
        if (kc < 7) { x0 = y0; x1 = y1; x2 = y2; x3 = y3; }
    }

    // ---- epilogue ----
#pragma unroll
    for (int nt = 0; nt < 8; nt++) {
        int colb = n0 + nt*8 + 2*c;
        *(float2*)&C[(m0 + g) * E_ + colb]     = make_float2(acc[nt][0], acc[nt][1]);
        *(float2*)&C[(m0 + g + 8) * E_ + colb] = make_float2(acc[nt][2], acc[nt][3]);
    }
}

// ---------------- Stage 2: per-bucket attention (1 warp / bucket) -----------
// Chunk-of-4 patch processing: all 8 K/V loads for a chunk issued before the
// softmax updates -> per-warp MLP 8 against L2 latency.
__global__ void __launch_bounds__(128) attn_kernel(const int* __restrict__ ign_p) {
    __shared__ int mem[4][CAP_];
    const int warp = threadIdx.x >> 5;
    const int lane = threadIdx.x & 31;
    const int n = blockIdx.x * 4 + warp;
    const int ign = *ign_p;

    int c = min(g_counts[n], CAP_);
    if (lane < c) mem[warp][lane] = g_members[n*CAP_ + lane];
    __syncwarp();
    if (lane == 0 && c > 1) {           // deterministic order
        int* a = mem[warp];
        for (int i = 1; i < c; i++) {
            int key = a[i]; int j = i - 1;
            while (j >= 0 && a[j] > key) { a[j+1] = a[j]; j--; }
            a[j+1] = key;
        }
    }
    __syncwarp();

    const int s = n & (S_ - 1);
    float4 q = *(const float4*)&g_Q[s*E_ + lane*4];

    const float* klast = ign ? g_Kfake : &g_Kon[n * E_];
    const float* vlast = ign ? g_Vfake : &g_Von[n * E_];

    float m = -INFINITY, lsum = 0.f;
    float4 acc = make_float4(0.f, 0.f, 0.f, 0.f);

    for (int base = 0; base <= c; base += 4) {
        const int cnt = min(4, c + 1 - base);
        float4 kb[4], vb[4];
#pragma unroll
        for (int j = 0; j < 4; j++) {
            if (j < cnt) {
                int p = base + j;
                const float *kr, *vr;
                if (p < c) {
                    int t = mem[warp][p];
                    kr = &g_Koff[(size_t)t * E_];
                    vr = &g_Voff[(size_t)t * E_];
                } else {
                    kr = klast; vr = vlast;
                }
                kb[j] = *(const float4*)&kr[lane*4];
                vb[j] = *(const float4*)&vr[lane*4];
            }
        }
#pragma unroll
        for (int j = 0; j < 4; j++) {
            if (j < cnt) {
                float d = q.x*kb[j].x + q.y*kb[j].y + q.z*kb[j].z + q.w*kb[j].w;
                d += __shfl_xor_sync(0xffffffffu, d, 1);
                d += __shfl_xor_sync(0xffffffffu, d, 2);   // head-group sum
                float sc = d * 0.25f;                      // 1/sqrt(DH=16)
                float mn = fmaxf(m, sc);
                float corr = expf(m - mn);
                float w = expf(sc - mn);
                lsum = lsum * corr + w;
                acc.x = acc.x*corr + w*vb[j].x;
                acc.y = acc.y*corr + w*vb[j].y;
                acc.z = acc.z*corr + w*vb[j].z;
                acc.w = acc.w*corr + w*vb[j].w;
                m = mn;
            }
        }
    }
    float inv = 1.0f / lsum;
    float4 o = make_float4(acc.x*inv, acc.y*inv, acc.z*inv, acc.w*inv);
    *(float4*)&g_attn[n*E_ + lane*4] = o;
}

// ---------------- Stage 3: Wo projection (32-row tiles, 512 CTAs) -----------
// 2-pass A-split (Ah*Wh + Al*Wh), Wh-only smem (34 KB) -> 6 CTAs/SM, 1 wave.
__global__ void __launch_bounds__(128, 6) wo_gemm(const float* __restrict__ attnA,
                                                  float* __restrict__ outC) {
    extern __shared__ uint32_t sw[];      // hi only: 64 x WROW
    const int tid = threadIdx.x;
    const float* A = attnA + (size_t)blockIdx.x * 32 * E_;
    float* C = outC + (size_t)blockIdx.x * 32 * E_;

    {
        const float4* srcH = (const float4*)g_Wp[3][0];
#pragma unroll
        for (int i = tid; i < 2048; i += 128) {
            int row = i >> 5;            // 0..63
            int c4  = i & 31;            // float4 within row
            *(float4*)&sw[row*WROW + c4*4] = srcH[i];
        }
    }
    __syncthreads();

    // 4 warps = 2 (M) x 2 (N); warp tile 16x64 over a 32x128 CTA tile
    const int wid  = tid >> 5;
    const int lane = tid & 31;
    const int m0 = (wid & 1) * 16;
    const int n0 = (wid >> 1) * 64;
    const int g = lane >> 2;
    const int c = lane & 3;

    float acc[8][4];
#pragma unroll
    for (int i = 0; i < 8; i++)
#pragma unroll
        for (int j = 0; j < 4; j++) acc[i][j] = 0.f;

    const float* ar = A + (m0 + g) * E_ + 2*c;
    float2 x0 = *(const float2*)ar;
    float2 x1 = *(const float2*)(ar + 8*E_);
    float2 x2 = *(const float2*)(ar + 8);
    float2 x3 = *(const float2*)(ar + 8*E_ + 8);

#pragma unroll
    for (int kc = 0; kc < 8; kc++) {
        float2 y0, y1, y2, y3;
        if (kc < 7) {
            const float* an = ar + (kc+1)*16;
            y0 = *(const float2*)an;
            y1 = *(const float2*)(an + 8*E_);
            y2 = *(const float2*)(an + 8);
            y3 = *(const float2*)(an + 8*E_ + 8);
        }
        uint32_t ah[4], al[4];
        ah[0] = pk2h(x0.x, x0.y);  al[0] = pk2h(residh(x0.x), residh(x0.y));
        ah[1] = pk2h(x1.x, x1.y);  al[1] = pk2h(residh(x1.x), residh(x1.y));
        ah[2] = pk2h(x2.x, x2.y);  al[2] = pk2h(residh(x2.x), residh(x2.y));
        ah[3] = pk2h(x3.x, x3.y);  al[3] = pk2h(residh(x3.x), residh(x3.y));

        const int brow = kc * 8 + c;
#pragma unroll
        for (int nt = 0; nt < 8; nt++) {
            int col = n0 + nt*8 + g;
            uint32_t bh0 = sw[brow*WROW + col];
            uint32_t bh1 = sw[(brow+4)*WROW + col];
            mma16816(acc[nt], ah, bh0, bh1);
            mma16816(acc[nt], al, bh0, bh1);
        }
        if (kc < 7) { x0 = y0; x1 = y1; x2 = y2; x3 = y3; }
    }

#pragma unroll
    for (int nt = 0; nt < 8; nt++) {
        int colb = n0 + nt*8 + 2*c;
        *(float2*)&C[(m0 + g) * E_ + colb]     = make_float2(acc[nt][0], acc[nt][1]);
        *(float2*)&C[(m0 + g + 8) * E_ + colb] = make_float2(acc[nt][2], acc[nt][3]);
    }
}

// ---------------- launcher ---------------------------------------------------
extern "C" void kernel_launch(void* const* d_in, const int* in_sizes, int n_in,
                              void* d_out, int out_size) {
    const float* xoff = (const float*)d_in[0];
    const float* xon  = (const float*)d_in[1];
    const float* zoff = (const float*)d_in[2];
    const float* zon  = (const float*)d_in[3];
    const float* lat  = (const float*)d_in[4];
    const float* fake = (const float*)d_in[5];
    const float* Wq   = (const float*)d_in[6];
    const float* Wk   = (const float*)d_in[7];
    const float* Wv   = (const float*)d_in[8];
    const float* Wo   = (const float*)d_in[9];
    const int*   ign  = (const int*)d_in[10];
    float* out = (float*)d_out;

    float* pAttn;
    cudaGetSymbolAddress((void**)&pAttn, g_attn);

    cudaFuncSetAttribute(gemm_mma,
                         cudaFuncAttributeMaxDynamicSharedMemorySize, W_BYTES);
    cudaFuncSetAttribute(wo_gemm,
                         cudaFuncAttributeMaxDynamicSharedMemorySize, WH_BYTES);

    // weight split + counts clear (fused)
    wsplit_kernel<<<64, 256>>>(Wq, Wk, Wv, Wo);

    // fused bucket(128) + fake(8) + K/V/Q GEMM(1600)
    gemm_mma<<<1736, 256, W_BYTES>>>(zoff, zon, lat, xoff, xon, fake, Wk, Wv);

    attn_kernel<<<NB_ / 4, 128>>>(ign);

    // output projection: 512 CTAs x 32-row tiles, single wave
    wo_gemm<<<512, 128, WH_BYTES>>>(pAttn, out);
}